// round 15
// baseline (speedup 1.0000x reference)
#include <cuda_runtime.h>
#include <cuda_fp16.h>
#include <math.h>
#include <stdint.h>

#define DHID 1536
#define SEQ  896
#define BAT  4
#define NMAX 5313
#define N0 5313
#define N1 1643
#define N2 128
#define WROWS (N0 + N1 + N2)

#define BM 128
#define BN 128
#define BK 64
#define NC (DHID / BK)        // 24

// ---------------- static device scratch ----------------
__device__ __align__(16) __half g_a[(size_t)BAT * SEQ * DHID];
__device__ __align__(16) __half g_w[(size_t)WROWS * DHID];

// ---------------- helpers ----------------
__device__ __forceinline__ uint32_t smem_u32(const void* p) {
    uint32_t a;
    asm("{ .reg .u64 t; cvta.to.shared.u64 t, %1; cvt.u32.u64 %0, t; }" : "=r"(a) : "l"(p));
    return a;
}
#define CP_ASYNC16(dst, src) \
    asm volatile("cp.async.cg.shared.global [%0], [%1], 16;" :: "r"(dst), "l"(src))
#define CP_COMMIT()  asm volatile("cp.async.commit_group;" ::: "memory")
#define CP_WAIT1()   asm volatile("cp.async.wait_group 1;" ::: "memory")

#define LDM_X4(r0,r1,r2,r3,addr) \
    asm volatile("ldmatrix.sync.aligned.m8n8.x4.shared.b16 {%0,%1,%2,%3}, [%4];" \
        : "=r"(r0),"=r"(r1),"=r"(r2),"=r"(r3) : "r"(addr))

#define MMA_F16(d, a0,a1,a2,a3, b0v, b1v) \
    asm volatile("mma.sync.aligned.m16n8k16.row.col.f32.f16.f16.f32 " \
        "{%0,%1,%2,%3}, {%4,%5,%6,%7}, {%8,%9}, {%0,%1,%2,%3};" \
        : "+f"((d)[0]), "+f"((d)[1]), "+f"((d)[2]), "+f"((d)[3]) \
        : "r"(a0), "r"(a1), "r"(a2), "r"(a3), "r"(b0v), "r"(b1v))

__device__ __forceinline__ float softplus_f(float z) {
    if (z > 20.0f) return z;
    return log1pf(__expf(z));
}

// ---------------- prep: LN->fp16 + W->fp16 (only needed heads) ----------------
__global__ void __launch_bounds__(256) prep_kernel(
    const float* __restrict__ x, const int* __restrict__ head_idx,
    const float* __restrict__ g0, const float* __restrict__ be0, const float* __restrict__ W0,
    const float* __restrict__ g1, const float* __restrict__ be1, const float* __restrict__ W1,
    const float* __restrict__ g2, const float* __restrict__ be2, const float* __restrict__ W2)
{
    int blk = blockIdx.x;
    int tid = threadIdx.x;

    if (blk < BAT * SEQ) {                     // ---- LayerNorm -> fp16 ----
        int row = blk;
        int b = row / SEQ;
        int head = head_idx[b];
        if (head >= 3) return;
        const float* gamma = (head == 0) ? g0 : (head == 1) ? g1 : g2;
        const float* beta  = (head == 0) ? be0 : (head == 1) ? be1 : be2;

        const float4* xr = (const float4*)(x + (size_t)row * DHID);
        float s = 0.f, ss = 0.f;
        for (int i = tid; i < DHID / 4; i += 256) {
            float4 t = xr[i];
            s  += t.x + t.y + t.z + t.w;
            ss += t.x * t.x + t.y * t.y + t.z * t.z + t.w * t.w;
        }
        __shared__ float red[64];
        #pragma unroll
        for (int o = 16; o > 0; o >>= 1) {
            s  += __shfl_down_sync(0xffffffffu, s,  o);
            ss += __shfl_down_sync(0xffffffffu, ss, o);
        }
        int wid = tid >> 5, lid = tid & 31;
        if (lid == 0) { red[wid] = s; red[32 + wid] = ss; }
        __syncthreads();
        __shared__ float mu_sh, rstd_sh;
        if (tid == 0) {
            float S1 = 0.f, S2 = 0.f;
            #pragma unroll
            for (int i = 0; i < 8; i++) { S1 += red[i]; S2 += red[32 + i]; }
            float mu = S1 / (float)DHID;
            float var = S2 / (float)DHID - mu * mu;
            mu_sh = mu; rstd_sh = rsqrtf(var + 1e-5f);
        }
        __syncthreads();
        float mu = mu_sh, rstd = rstd_sh;
        const float4* gv = (const float4*)gamma;
        const float4* bv = (const float4*)beta;
        uint2* ro = (uint2*)(g_a + (size_t)row * DHID);
        for (int i = tid; i < DHID / 4; i += 256) {
            float4 t = xr[i], g = gv[i], be = bv[i];
            __align__(8) __half h[4];
            h[0] = __float2half((t.x - mu) * rstd * g.x + be.x);
            h[1] = __float2half((t.y - mu) * rstd * g.y + be.y);
            h[2] = __float2half((t.z - mu) * rstd * g.z + be.z);
            h[3] = __float2half((t.w - mu) * rstd * g.w + be.w);
            ro[i] = *(uint2*)h;
        }
    } else {                                   // ---- W -> fp16 (needed heads only) ----
        int mask = (1 << head_idx[0]) | (1 << head_idx[1]) |
                   (1 << head_idx[2]) | (1 << head_idx[3]);
        size_t wb = blk - BAT * SEQ;
        size_t base = wb * 2048 + (size_t)tid * 8;
        const size_t B0 = (size_t)N0 * DHID, B1 = B0 + (size_t)N1 * DHID;
        const float* src;
        int h;
        if (base < B0)      { src = W0 + base;        h = 0; }
        else if (base < B1) { src = W1 + (base - B0); h = 1; }
        else                { src = W2 + (base - B1); h = 2; }
        if (!(mask & (1 << h))) return;
        float4 v0 = ((const float4*)src)[0];
        float4 v1 = ((const float4*)src)[1];
        __align__(16) __half hh[8];
        hh[0] = __float2half(v0.x); hh[1] = __float2half(v0.y);
        hh[2] = __float2half(v0.z); hh[3] = __float2half(v0.w);
        hh[4] = __float2half(v1.x); hh[5] = __float2half(v1.y);
        hh[6] = __float2half(v1.z); hh[7] = __float2half(v1.w);
        *(uint4*)(g_w + base) = *(uint4*)hh;
    }
}

// ---------------- HMMA GEMM: 128 thr, 2x2 warps of 64x64, BK=64, 3-stage, B-frag DB ----------------
#define ROWB   144                   // 128B data + 16B pad
#define MATB   (128 * ROWB)          // 18432
#define STGB   (2 * MATB)            // 36864 : A + B per stage
#define A_OFF(s) ((s) * STGB)
#define B_OFF(s) ((s) * STGB + MATB)
#define SMEM_TOTAL (3 * STGB)        // 110592

__global__ void __launch_bounds__(128, 2) head_gemm_mma(
    const int* __restrict__ head_idx,
    const float* __restrict__ b0p, const float* __restrict__ b1p, const float* __restrict__ b2p,
    float* __restrict__ out)
{
    extern __shared__ char smem[];
    int tid = threadIdx.x;
    int bz = blockIdx.z;
    int row0 = blockIdx.y * BM;
    int col0 = blockIdx.x * BN;

    int head = head_idx[bz];
    int n; const __half* wmat;
    if (head == 0)      { n = N0; wmat = g_w; }
    else if (head == 1) { n = N1; wmat = g_w + (size_t)N0 * DHID; }
    else if (head == 2) { n = N2; wmat = g_w + (size_t)(N0 + N1) * DHID; }
    else                { n = 0; wmat = nullptr; }

    float* outb = out + (size_t)bz * SEQ * NMAX;
    int wid = tid >> 5, lid = tid & 31;

    if (col0 >= n) {            // padding / ZeroHead tile: vectorized zero-fill
        int len = NMAX - col0; if (len > BN) len = BN;
        if (len > 0) {
            for (int r = wid; r < BM; r += 4) {
                float* p = outb + (size_t)(row0 + r) * NMAX + col0;
                uint32_t mis = ((uint32_t)(uintptr_t)p >> 2) & 3;
                int head_n = (int)((4 - mis) & 3);
                if (head_n > len) head_n = len;
                if (lid < head_n) p[lid] = 0.f;
                int body = (len - head_n) >> 2;
                float4* pb = (float4*)(p + head_n);
                for (int i = lid; i < body; i += 32)
                    pb[i] = make_float4(0.f, 0.f, 0.f, 0.f);
                int t = head_n + body * 4 + lid;
                if (t < len) p[t] = 0.f;
            }
        }
        return;
    }

    uint32_t sb = smem_u32(smem);
    int wm = wid >> 1;          // 0..1  (64 rows each)
    int wn = wid & 1;           // 0..1  (64 cols each)

    const __half* amat = g_a + ((size_t)bz * SEQ + row0) * DHID;

    // chunk = BK=64 halves = 128B per row, 8 segs of 16B per row
    auto load_chunk = [&](int c, int s) {
        int k0 = c * BK;
        #pragma unroll 2
        for (int t = 0; t < 8; t++) {
            int u = tid + t * 128;         // 0..1023
            int row = u >> 3, seg = u & 7;
            uint32_t dof = (uint32_t)row * ROWB + (uint32_t)seg * 16;
            CP_ASYNC16(sb + A_OFF(s) + dof,
                       (const char*)(amat + (size_t)row * DHID + k0) + seg * 16);
            int gr = col0 + row;
            uint32_t d = sb + B_OFF(s) + dof;
            if (gr < n) {
                CP_ASYNC16(d, (const char*)(wmat + (size_t)gr * DHID + k0) + seg * 16);
            } else {
                asm volatile("st.shared.v4.b32 [%0], {%1,%1,%1,%1};" :: "r"(d), "r"(0u) : "memory");
            }
        }
    };

    float acc[4][8][4];                 // 128 regs: mi x (g*2+h) x 4
    #pragma unroll
    for (int i = 0; i < 4; i++)
        #pragma unroll
        for (int j = 0; j < 8; j++)
            #pragma unroll
            for (int k = 0; k < 4; k++) acc[i][j][k] = 0.f;

    load_chunk(0, 0); CP_COMMIT();
    load_chunk(1, 1); CP_COMMIT();

    // ldmatrix lane addressing (constant across chunks)
    uint32_t aRow = (uint32_t)(wm * 64 + (lid & 15)) * ROWB + (uint32_t)(lid >> 4) * 16;
    int q = lid >> 3;
    uint32_t bRowBase = (uint32_t)(wn * 64 + ((q >> 1) << 3) + (lid & 7)) * ROWB + (uint32_t)(q & 1) * 16;

    uint32_t bf[2][4][4];               // B-frag double buffer: 32 regs

    for (int c = 0; c < NC; c++) {
        int s = c - (c / 3) * 3;            // c % 3
        CP_WAIT1();              // chunk c resident (chunk c+1 may still fly)
        __syncthreads();         // + all warps finished compute(c-1)

        // preload B frags for kk=0
        #pragma unroll
        for (int g = 0; g < 4; g++) {
            uint32_t rb = sb + B_OFF(s) + bRowBase + (uint32_t)(g * 16) * ROWB;
            LDM_X4(bf[0][g][0], bf[0][g][1], bf[0][g][2], bf[0][g][3], rb);
        }

        #pragma unroll
        for (int kk = 0; kk < 4; kk++) {
            int cur = kk & 1, nxt = cur ^ 1;
            uint32_t kb = (uint32_t)kk * 32;
            #pragma unroll
            for (int mi = 0; mi < 4; mi++) {
                uint32_t ra = sb + A_OFF(s) + aRow + (uint32_t)(mi * 16) * ROWB + kb;
                uint32_t a0, a1, a2, a3;
                LDM_X4(a0, a1, a2, a3, ra);
                if (kk < 3) {
                    // prefetch one B group of kk+1 per mi iteration (interleaved)
                    uint32_t rb = sb + B_OFF(s) + bRowBase + (uint32_t)(mi * 16) * ROWB + kb + 32;
                    LDM_X4(bf[nxt][mi][0], bf[nxt][mi][1], bf[nxt][mi][2], bf[nxt][mi][3], rb);
                }
                #pragma unroll
                for (int g = 0; g < 4; g++)
                    #pragma unroll
                    for (int h = 0; h < 2; h++)
                        MMA_F16(acc[mi][2 * g + h], a0, a1, a2, a3,
                                bf[cur][g][2 * h], bf[cur][g][2 * h + 1]);
            }
            if (kk == 0) {
                // issue next-next chunk loads after the post-barrier LDSM burst
                if (c + 2 < NC) {
                    int s2 = (c + 2) - ((c + 2) / 3) * 3;
                    load_chunk(c + 2, s2);
                }
                CP_COMMIT();     // unconditional: keeps group accounting aligned
            }
        }
    }

    // ---- epilogue: bias + softplus + zero-pad (scalar stores; NMAX odd) ----
    const float* bias = (head == 0) ? b0p : (head == 1) ? b1p : b2p;
    #pragma unroll
    for (int mi = 0; mi < 4; mi++) {
        int r = row0 + wm * 64 + mi * 16 + (lid >> 2);
        float* o0 = outb + (size_t)r * NMAX;
        float* o1 = o0 + 8 * NMAX;
        #pragma unroll
        for (int nf = 0; nf < 8; nf++) {
            int cc = col0 + wn * 64 + nf * 8 + (lid & 3) * 2;
            float* a = acc[mi][nf];
            #pragma unroll
            for (int j = 0; j < 2; j++) {
                int c = cc + j;
                if (c < n) {
                    float bv = bias[c];
                    o0[c] = softplus_f(a[0 + j] + bv);
                    o1[c] = softplus_f(a[2 + j] + bv);
                } else if (c < NMAX) {
                    o0[c] = 0.f;
                    o1[c] = 0.f;
                }
            }
        }
    }
}

// ---------------- launch ----------------
extern "C" void kernel_launch(void* const* d_in, const int* in_sizes, int n_in,
                              void* d_out, int out_size) {
    const float* x        = (const float*)d_in[0];
    const int*   head_idx = (const int*)d_in[1];
    const float* g0 = (const float*)d_in[2];
    const float* be0 = (const float*)d_in[3];
    const float* W0 = (const float*)d_in[4];
    const float* bb0 = (const float*)d_in[5];
    const float* g1 = (const float*)d_in[6];
    const float* be1 = (const float*)d_in[7];
    const float* W1 = (const float*)d_in[8];
    const float* bb1 = (const float*)d_in[9];
    const float* g2 = (const float*)d_in[10];
    const float* be2 = (const float*)d_in[11];
    const float* W2 = (const float*)d_in[12];
    const float* bb2 = (const float*)d_in[13];
    float* out = (float*)d_out;

    int wblocks = (int)(((size_t)WROWS * DHID) / 2048);   // 5313
    prep_kernel<<<BAT * SEQ + wblocks, 256>>>(x, head_idx,
                                              g0, be0, W0, g1, be1, W1, g2, be2, W2);

    cudaFuncSetAttribute(head_gemm_mma, cudaFuncAttributeMaxDynamicSharedMemorySize, SMEM_TOTAL);
    dim3 grid((NMAX + BN - 1) / BN, SEQ / BM, BAT);   // 42 x 7 x 4
    head_gemm_mma<<<grid, 128, SMEM_TOTAL>>>(head_idx, bb0, bb1, bb2, out);
}

// round 16
// speedup vs baseline: 1.2456x; 1.2456x over previous
#include <cuda_runtime.h>
#include <cuda_fp16.h>
#include <math.h>
#include <stdint.h>

#define DHID 1536
#define SEQ  896
#define BAT  4
#define NMAX 5313
#define N0 5313
#define N1 1643
#define N2 128
#define WROWS (N0 + N1 + N2)

#define BM 128
#define BN 128
#define BK 64
#define NC (DHID / BK)        // 24

// ---------------- static device scratch ----------------
__device__ __align__(16) __half g_a[(size_t)BAT * SEQ * DHID];
__device__ __align__(16) __half g_w[(size_t)WROWS * DHID];

// ---------------- helpers ----------------
__device__ __forceinline__ uint32_t smem_u32(const void* p) {
    uint32_t a;
    asm("{ .reg .u64 t; cvta.to.shared.u64 t, %1; cvt.u32.u64 %0, t; }" : "=r"(a) : "l"(p));
    return a;
}
#define CP_ASYNC16(dst, src) \
    asm volatile("cp.async.cg.shared.global [%0], [%1], 16;" :: "r"(dst), "l"(src))
#define CP_COMMIT()  asm volatile("cp.async.commit_group;" ::: "memory")
#define CP_WAIT1()   asm volatile("cp.async.wait_group 1;" ::: "memory")

#define LDM_X4(r0,r1,r2,r3,addr) \
    asm volatile("ldmatrix.sync.aligned.m8n8.x4.shared.b16 {%0,%1,%2,%3}, [%4];" \
        : "=r"(r0),"=r"(r1),"=r"(r2),"=r"(r3) : "r"(addr))

#define MMA_F16(d, a0,a1,a2,a3, b0v, b1v) \
    asm volatile("mma.sync.aligned.m16n8k16.row.col.f32.f16.f16.f32 " \
        "{%0,%1,%2,%3}, {%4,%5,%6,%7}, {%8,%9}, {%0,%1,%2,%3};" \
        : "+f"((d)[0]), "+f"((d)[1]), "+f"((d)[2]), "+f"((d)[3]) \
        : "r"(a0), "r"(a1), "r"(a2), "r"(a3), "r"(b0v), "r"(b1v))

__device__ __forceinline__ float softplus_f(float z) {
    if (z > 20.0f) return z;
    return log1pf(__expf(z));
}

// ---------------- prep: LN->fp16 + W->fp16 (only needed heads) ----------------
__global__ void __launch_bounds__(256) prep_kernel(
    const float* __restrict__ x, const int* __restrict__ head_idx,
    const float* __restrict__ g0, const float* __restrict__ be0, const float* __restrict__ W0,
    const float* __restrict__ g1, const float* __restrict__ be1, const float* __restrict__ W1,
    const float* __restrict__ g2, const float* __restrict__ be2, const float* __restrict__ W2)
{
    int blk = blockIdx.x;
    int tid = threadIdx.x;

    if (blk < BAT * SEQ) {                     // ---- LayerNorm -> fp16 ----
        int row = blk;
        int b = row / SEQ;
        int head = head_idx[b];
        if (head >= 3) return;
        const float* gamma = (head == 0) ? g0 : (head == 1) ? g1 : g2;
        const float* beta  = (head == 0) ? be0 : (head == 1) ? be1 : be2;

        const float4* xr = (const float4*)(x + (size_t)row * DHID);
        float s = 0.f, ss = 0.f;
        for (int i = tid; i < DHID / 4; i += 256) {
            float4 t = xr[i];
            s  += t.x + t.y + t.z + t.w;
            ss += t.x * t.x + t.y * t.y + t.z * t.z + t.w * t.w;
        }
        __shared__ float red[64];
        #pragma unroll
        for (int o = 16; o > 0; o >>= 1) {
            s  += __shfl_down_sync(0xffffffffu, s,  o);
            ss += __shfl_down_sync(0xffffffffu, ss, o);
        }
        int wid = tid >> 5, lid = tid & 31;
        if (lid == 0) { red[wid] = s; red[32 + wid] = ss; }
        __syncthreads();
        __shared__ float mu_sh, rstd_sh;
        if (tid == 0) {
            float S1 = 0.f, S2 = 0.f;
            #pragma unroll
            for (int i = 0; i < 8; i++) { S1 += red[i]; S2 += red[32 + i]; }
            float mu = S1 / (float)DHID;
            float var = S2 / (float)DHID - mu * mu;
            mu_sh = mu; rstd_sh = rsqrtf(var + 1e-5f);
        }
        __syncthreads();
        float mu = mu_sh, rstd = rstd_sh;
        const float4* gv = (const float4*)gamma;
        const float4* bv = (const float4*)beta;
        uint2* ro = (uint2*)(g_a + (size_t)row * DHID);
        for (int i = tid; i < DHID / 4; i += 256) {
            float4 t = xr[i], g = gv[i], be = bv[i];
            __align__(8) __half h[4];
            h[0] = __float2half((t.x - mu) * rstd * g.x + be.x);
            h[1] = __float2half((t.y - mu) * rstd * g.y + be.y);
            h[2] = __float2half((t.z - mu) * rstd * g.z + be.z);
            h[3] = __float2half((t.w - mu) * rstd * g.w + be.w);
            ro[i] = *(uint2*)h;
        }
    } else {                                   // ---- W -> fp16 (needed heads only) ----
        int mask = (1 << head_idx[0]) | (1 << head_idx[1]) |
                   (1 << head_idx[2]) | (1 << head_idx[3]);
        size_t wb = blk - BAT * SEQ;
        size_t base = wb * 2048 + (size_t)tid * 8;
        const size_t B0 = (size_t)N0 * DHID, B1 = B0 + (size_t)N1 * DHID;
        const float* src;
        int h;
        if (base < B0)      { src = W0 + base;        h = 0; }
        else if (base < B1) { src = W1 + (base - B0); h = 1; }
        else                { src = W2 + (base - B1); h = 2; }
        if (!(mask & (1 << h))) return;
        float4 v0 = ((const float4*)src)[0];
        float4 v1 = ((const float4*)src)[1];
        __align__(16) __half hh[8];
        hh[0] = __float2half(v0.x); hh[1] = __float2half(v0.y);
        hh[2] = __float2half(v0.z); hh[3] = __float2half(v0.w);
        hh[4] = __float2half(v1.x); hh[5] = __float2half(v1.y);
        hh[6] = __float2half(v1.z); hh[7] = __float2half(v1.w);
        *(uint4*)(g_w + base) = *(uint4*)hh;
    }
}

// ---------------- HMMA GEMM (R10 structure: fp16, BK=64, 3-stage depth-2) ----------------
#define ROWB   144                   // 128B data + 16B pad
#define MATB   (128 * ROWB)          // 18432
#define STGB   (2 * MATB)            // 36864 : A + B per stage
#define A_OFF(s) ((s) * STGB)
#define B_OFF(s) ((s) * STGB + MATB)
#define SMEM_TOTAL (3 * STGB)        // 110592

__global__ void __launch_bounds__(256, 2) head_gemm_mma(
    const int* __restrict__ head_idx,
    const float* __restrict__ b0p, const float* __restrict__ b1p, const float* __restrict__ b2p,
    float* __restrict__ out)
{
    extern __shared__ char smem[];
    int tid = threadIdx.x;
    int bz = blockIdx.z;
    int row0 = blockIdx.y * BM;
    int col0 = blockIdx.x * BN;

    int head = head_idx[bz];
    int n; const __half* wmat; const float* bias;
    if (head == 0)      { n = N0; wmat = g_w; bias = b0p; }
    else if (head == 1) { n = N1; wmat = g_w + (size_t)N0 * DHID; bias = b1p; }
    else if (head == 2) { n = N2; wmat = g_w + (size_t)(N0 + N1) * DHID; bias = b2p; }
    else                { n = 0; wmat = nullptr; bias = nullptr; }

    float* outb = out + (size_t)bz * SEQ * NMAX;
    int wid = tid >> 5, lid = tid & 31;

    if (col0 >= n) {            // padding / ZeroHead tile: vectorized zero-fill
        int len = NMAX - col0; if (len > BN) len = BN;
        if (len > 0) {
            for (int r = wid; r < BM; r += 8) {
                float* p = outb + (size_t)(row0 + r) * NMAX + col0;
                uint32_t mis = ((uint32_t)(uintptr_t)p >> 2) & 3;
                int head_n = (int)((4 - mis) & 3);
                if (head_n > len) head_n = len;
                if (lid < head_n) p[lid] = 0.f;
                int body = (len - head_n) >> 2;
                float4* pb = (float4*)(p + head_n);
                for (int i = lid; i < body; i += 32)
                    pb[i] = make_float4(0.f, 0.f, 0.f, 0.f);
                int t = head_n + body * 4 + lid;
                if (t < len) p[t] = 0.f;
            }
        }
        return;
    }

    uint32_t sb = smem_u32(smem);
    int wm = wid >> 2;          // 0..1  (64 rows each)
    int wn = wid & 3;           // 0..3  (32 cols each)

    const __half* amat = g_a + ((size_t)bz * SEQ + row0) * DHID;

    // chunk = BK=64 halves = 128B per row, 8 segs of 16B per row
    auto load_chunk = [&](int c, int s) {
        int k0 = c * BK;
        #pragma unroll
        for (int t = 0; t < 4; t++) {
            int u = tid + t * 256;         // 0..1023
            int row = u >> 3, seg = u & 7;
            uint32_t dof = (uint32_t)row * ROWB + (uint32_t)seg * 16;
            CP_ASYNC16(sb + A_OFF(s) + dof,
                       (const char*)(amat + (size_t)row * DHID + k0) + seg * 16);
            int gr = col0 + row;
            uint32_t d = sb + B_OFF(s) + dof;
            if (gr < n) {
                CP_ASYNC16(d, (const char*)(wmat + (size_t)gr * DHID + k0) + seg * 16);
            } else {
                asm volatile("st.shared.v4.b32 [%0], {%1,%1,%1,%1};" :: "r"(d), "r"(0u) : "memory");
            }
        }
    };

    float acc[4][4][4];
    #pragma unroll
    for (int i = 0; i < 4; i++)
        #pragma unroll
        for (int j = 0; j < 4; j++)
            #pragma unroll
            for (int k = 0; k < 4; k++) acc[i][j][k] = 0.f;

    load_chunk(0, 0); CP_COMMIT();
    load_chunk(1, 1); CP_COMMIT();

    // ldmatrix lane addressing (constant across chunks)
    uint32_t aRow = (uint32_t)(wm * 64 + (lid & 15)) * ROWB + (uint32_t)(lid >> 4) * 16;
    int q = lid >> 3;
    uint32_t bRowBase = (uint32_t)(wn * 32 + ((q >> 1) << 3) + (lid & 7)) * ROWB + (uint32_t)(q & 1) * 16;

    #pragma unroll 3
    for (int c = 0; c < NC; c++) {
        int s = c - (c / 3) * 3;            // c % 3 : compile-time under unroll-by-3
        CP_WAIT1();              // chunk c resident (chunk c+1 may still fly)
        __syncthreads();         // + all warps finished compute(c-1)

        #pragma unroll
        for (int kk = 0; kk < 4; kk++) {
            uint32_t kb = (uint32_t)kk * 32;
            uint32_t bf[2][4];
            #pragma unroll
            for (int g = 0; g < 2; g++) {
                uint32_t rb = sb + B_OFF(s) + bRowBase + (uint32_t)(g * 16) * ROWB + kb;
                LDM_X4(bf[g][0], bf[g][1], bf[g][2], bf[g][3], rb);
            }
            #pragma unroll
            for (int mi = 0; mi < 4; mi++) {
                uint32_t ra = sb + A_OFF(s) + aRow + (uint32_t)(mi * 16) * ROWB + kb;
                uint32_t a0, a1, a2, a3;
                LDM_X4(a0, a1, a2, a3, ra);
                #pragma unroll
                for (int g = 0; g < 2; g++)
                    #pragma unroll
                    for (int h = 0; h < 2; h++)
                        MMA_F16(acc[mi][2 * g + h], a0, a1, a2, a3, bf[g][2 * h], bf[g][2 * h + 1]);
            }
            if (kk == 0) {
                // issue next-next chunk loads after the post-barrier LDSM burst
                if (c + 2 < NC) {
                    int s2 = (c + 2) - ((c + 2) / 3) * 3;
                    load_chunk(c + 2, s2);
                }
                CP_COMMIT();     // unconditional: keeps group accounting aligned
            }
        }
    }

    // ---- epilogue: bias + softplus + zero-pad (scalar stores; NMAX odd) ----
    #pragma unroll
    for (int mi = 0; mi < 4; mi++) {
        int r = row0 + wm * 64 + mi * 16 + (lid >> 2);
        float* o0 = outb + (size_t)r * NMAX;
        float* o1 = o0 + 8 * NMAX;
        #pragma unroll
        for (int ni = 0; ni < 4; ni++) {
            int cc = col0 + wn * 32 + ni * 8 + (lid & 3) * 2;
            float* a = acc[mi][ni];
            #pragma unroll
            for (int j = 0; j < 2; j++) {
                int c = cc + j;
                if (c < n) {
                    float bv = bias[c];
                    o0[c] = softplus_f(a[0 + j] + bv);
                    o1[c] = softplus_f(a[2 + j] + bv);
                } else if (c < NMAX) {
                    o0[c] = 0.f;
                    o1[c] = 0.f;
                }
            }
        }
    }
}

// ---------------- launch ----------------
extern "C" void kernel_launch(void* const* d_in, const int* in_sizes, int n_in,
                              void* d_out, int out_size) {
    const float* x        = (const float*)d_in[0];
    const int*   head_idx = (const int*)d_in[1];
    const float* g0 = (const float*)d_in[2];
    const float* be0 = (const float*)d_in[3];
    const float* W0 = (const float*)d_in[4];
    const float* bb0 = (const float*)d_in[5];
    const float* g1 = (const float*)d_in[6];
    const float* be1 = (const float*)d_in[7];
    const float* W1 = (const float*)d_in[8];
    const float* bb1 = (const float*)d_in[9];
    const float* g2 = (const float*)d_in[10];
    const float* be2 = (const float*)d_in[11];
    const float* W2 = (const float*)d_in[12];
    const float* bb2 = (const float*)d_in[13];
    float* out = (float*)d_out;

    int wblocks = (int)(((size_t)WROWS * DHID) / 2048);   // 5313
    prep_kernel<<<BAT * SEQ + wblocks, 256>>>(x, head_idx,
                                              g0, be0, W0, g1, be1, W1, g2, be2, W2);

    cudaFuncSetAttribute(head_gemm_mma, cudaFuncAttributeMaxDynamicSharedMemorySize, SMEM_TOTAL);
    dim3 grid((NMAX + BN - 1) / BN, SEQ / BM, BAT);   // 42 x 7 x 4
    head_gemm_mma<<<grid, 256, SMEM_TOTAL>>>(head_idx, bb0, bb1, bb2, out);
}